// round 12
// baseline (speedup 1.0000x reference)
#include <cuda_runtime.h>
#include <cstddef>

#define B 16
#define N 1024
#define P 256
#define D 64
#define K 26
#define S 4                 // n-segments (8192 streaming warps)
#define NSEG (N / S)        // 256 n per segment

#define PROD_CTAS 128       // importance producer CTAs (bids 0..127)
#define STREAM_CTAS (S * B * (P / 2) / 4)   // 2048 (128-thr CTAs, 4 warps)
#define CTAS_PER_BATCH (STREAM_CTAS / B)    // 128
#define NSLOTS_PER_CTA (N / CTAS_PER_BATCH) // 8

#define KD4 (K * D / 4)     // 416 float4 per anchor block

// ---- scratch (no allocations allowed; device globals) ----
__device__ float g_importance[N];            // [n]
__device__ float g_pscore[S * B * P];        // [s, b*P+p] partial scores
__device__ float g_pmean[S * B * P * D];     // [s, b*P+p, d] partial sums
__device__ float g_anchor[B * K * D];        // [b, k, d] finalized anchors
__device__ int   g_done;                     // importance-producer counter
__device__ int   g_cnt[B];                   // per-batch streamer-arrival counters
__device__ int   g_ready[B];                 // per-batch anchor-ready flags
__device__ int   g_fin;                      // retire counter (drives reset)

// ------------------------------------------------------------------
// ONE persistent kernel, three roles by bid:
//  bid < 128: PRODUCER  — importance cols, publish, bump g_done, exit.
//  else:      STREAMER  — batch-major (b, seg, pgroup). Stream NSEG n's
//             (half-warp per p, contiguous 512B per warp-iter), stash
//             norms in smem, defer the importance dot behind a g_done
//             spin (expected wait ~0). Arrive at g_cnt[b]; the LAST
//             arriver finalizes batch b (score reduce -> stable top-k
//             matching jax.lax.top_k (descending, low index wins ties)
//             -> anchor reduce -> g_anchor[b]) and sets g_ready[b].
//             Then ALL 128 CTAs of batch b replicate the anchor block
//             to their 8 n-slots — overlapping later batches' streams.
//             2048th retiree resets all counters for the next replay.
// Deadlock-free: producers never wait; g_ready[b] is set by the last
// arriver of batch b, which is by construction already running.
// ------------------------------------------------------------------
__global__ void __launch_bounds__(128) k_all(const float* __restrict__ patches,
                                             const float* __restrict__ adp,
                                             float* __restrict__ out) {
    __shared__ float snorm[8][NSEG];    // per half-warp norms (8 KB)
    __shared__ float simp[NSEG];        // importance segment (1 KB)
    __shared__ float red[16][8];        // producer reduce
    __shared__ float sc[P];             // finalizer: reduced scores
    __shared__ int   tk[K];             // finalizer: top-k indices
    __shared__ int   s_islast;

    int tid = threadIdx.x;
    int bid = blockIdx.x;

    if (bid < PROD_CTAS) {
        // ---------------- producer: 8 columns of adp ----------------
        int jl   = tid & 7;
        int iseg = tid >> 3;             // 0..15, 64 rows each
        int j    = bid * 8 + jl;

        float s = 0.f;
        const float* col = adp + (size_t)(iseg * 64) * N + j;
#pragma unroll 8
        for (int i = 0; i < 64; i++) s += col[(size_t)i * N];
        red[iseg][jl] = s;
        __syncthreads();
        if (tid < 8) {
            float t = 0.f;
#pragma unroll
            for (int r = 0; r < 16; r++) t += red[r][tid];
            g_importance[j - jl + tid] = t * (1.0f / (float)N);
        }
        __threadfence();
        __syncthreads();
        if (tid == 0) atomicAdd(&g_done, 1);
        return;
    }

    // ---------------- streamer (batch-major ordering) ----------------
    int sid    = bid - PROD_CTAS;        // 0..2047
    int b      = sid >> 7;               // batch (CTA-uniform)
    int within = sid & 127;              // 0..127 within batch
    int seg    = within >> 5;            // 0..3
    int pg     = within & 31;            // p-group (4 warps = 8 p's)
    int warp   = tid >> 5;
    int lane   = tid & 31;
    int half   = lane >> 4;
    int hl     = lane & 15;
    int hw     = tid >> 4;

    int p  = (pg * 4 + warp) * 2 + half;
    int n0 = seg * NSEG;

    const float4* base =
        (const float4*)(patches + (((size_t)b * N + n0) * P + p) * (size_t)D) + hl;
    const size_t nstride = (size_t)P * D / 4;

    float4 ms = make_float4(0.f, 0.f, 0.f, 0.f);

#pragma unroll 8
    for (int n = 0; n < NSEG; n++) {
        float4 v = __ldcs(base + (size_t)n * nstride);   // streaming, read-once
        ms.x += v.x; ms.y += v.y; ms.z += v.z; ms.w += v.w;
        float sq = v.x * v.x + v.y * v.y + v.z * v.z + v.w * v.w;
        sq += __shfl_xor_sync(0xffffffffu, sq, 8);
        sq += __shfl_xor_sync(0xffffffffu, sq, 4);
        sq += __shfl_xor_sync(0xffffffffu, sq, 2);
        sq += __shfl_xor_sync(0xffffffffu, sq, 1);
        if (hl == 0) snorm[hw][n] = sqrtf(sq);
    }

    size_t bp = (size_t)b * P + p;
    ((float4*)g_pmean)[((size_t)seg * B * P + bp) * (D / 4) + hl] = ms;

    // importance dot (producers finished long ago)
    if (tid == 0) {
        while (*(volatile int*)&g_done != PROD_CTAS) { __nanosleep(100); }
    }
    __syncthreads();
    __threadfence();                     // acquire
    if (tid < 128) {
        simp[tid]       = g_importance[n0 + tid];
        simp[tid + 128] = g_importance[n0 + tid + 128];
    }
    __syncthreads();

    float acc = 0.f;
#pragma unroll
    for (int t = 0; t < 16; t++) {
        int n = hl + 16 * t;
        acc += snorm[hw][n] * simp[n];
    }
    acc += __shfl_xor_sync(0xffffffffu, acc, 8);
    acc += __shfl_xor_sync(0xffffffffu, acc, 4);
    acc += __shfl_xor_sync(0xffffffffu, acc, 2);
    acc += __shfl_xor_sync(0xffffffffu, acc, 1);
    if (hl == 0) g_pscore[(size_t)seg * B * P + bp] = acc;

    // ---------------- batch arrival + finalizer election ----------------
    __threadfence();                     // publish pscore/pmean
    __syncthreads();
    if (tid == 0) {
        int old = atomicAdd(&g_cnt[b], 1);
        s_islast = (old == CTAS_PER_BATCH - 1);
    }
    __syncthreads();

    if (s_islast) {
        __threadfence();                 // acquire all batch-b partials

        // 1. reduce partial scores (fixed order -> deterministic)
        for (int pp = tid; pp < P; pp += 128) {
            float v = 0.f;
#pragma unroll
            for (int s = 0; s < S; s++) v += g_pscore[s * B * P + b * P + pp];
            sc[pp] = v;
        }
        __syncthreads();

        // 2. stable rank-count top-k
        for (int pp = tid; pp < P; pp += 128) {
            float my = sc[pp];
            int rank = 0;
#pragma unroll 8
            for (int q = 0; q < P; q++) {
                float v = sc[q];
                rank += (v > my) || (v == my && q < pp);
            }
            if (rank < K) tk[rank] = pp;
        }
        __syncthreads();

        // 3. reduce + scale the 26x64 anchor block
        const int MF4 = B * P * D / 4;
        const float inv = 1.0f / (float)N;
        for (int t = tid; t < KD4; t += 128) {
            int kk  = t >> 4;
            int dd4 = t & 15;
            size_t idx = ((size_t)b * P + tk[kk]) * (D / 4) + dd4;
            float4 a = make_float4(0.f, 0.f, 0.f, 0.f);
#pragma unroll
            for (int s = 0; s < S; s++) {
                float4 v = ((const float4*)g_pmean)[(size_t)s * MF4 + idx];
                a.x += v.x; a.y += v.y; a.z += v.z; a.w += v.w;
            }
            ((float4*)g_anchor)[(size_t)b * KD4 + t] =
                make_float4(a.x * inv, a.y * inv, a.z * inv, a.w * inv);
        }
        __syncthreads();
        __threadfence();
        if (tid == 0) atomicExch(&g_ready[b], 1);
    }

    // ---------------- replicate: 8 n-slots per CTA ----------------
    if (tid == 0) {
        while (*(volatile int*)&g_ready[b] == 0) { __nanosleep(200); }
    }
    __syncthreads();
    __threadfence();                     // acquire g_anchor[b]

    int t0 = tid, t1 = tid + 128, t2 = tid + 256, t3 = tid + 384;
    const float4* anc = (const float4*)g_anchor + (size_t)b * KD4;
    float4 a0 = anc[t0];
    float4 a1 = anc[t1];
    float4 a2 = anc[t2];
    float4 a3 = (t3 < KD4) ? anc[t3] : make_float4(0, 0, 0, 0);

    float4* obase = (float4*)out +
                    ((size_t)b * N + (size_t)within * NSLOTS_PER_CTA) * KD4;
#pragma unroll
    for (int nn = 0; nn < NSLOTS_PER_CTA; nn++) {
        float4* o = obase + (size_t)nn * KD4;
        __stcs(o + t0, a0);
        __stcs(o + t1, a1);
        __stcs(o + t2, a2);
        if (t3 < KD4) __stcs(o + t3, a3);
    }

    // ---------------- retire + counter reset for next replay ----------------
    __syncthreads();
    if (tid == 0) {
        int o = atomicAdd(&g_fin, 1);
        if (o == STREAM_CTAS - 1) {      // every CTA has passed all spins
            g_done = 0;
            g_fin  = 0;
#pragma unroll
            for (int i = 0; i < B; i++) { g_cnt[i] = 0; g_ready[i] = 0; }
            __threadfence();
        }
    }
}

// ------------------------------------------------------------------
extern "C" void kernel_launch(void* const* d_in, const int* in_sizes, int n_in,
                              void* d_out, int out_size) {
    const float* patches = (const float*)d_in[0];
    const float* adp     = (const float*)d_in[1];
    if (n_in >= 2 && in_sizes[0] == N * N && in_sizes[1] == B * N * P * D) {
        const float* t = patches; patches = adp; adp = t;
    }
    float* out = (float*)d_out;

    k_all<<<PROD_CTAS + STREAM_CTAS, 128>>>(patches, adp, out);
}